// round 7
// baseline (speedup 1.0000x reference)
#include <cuda_runtime.h>
#include <cuda_bf16.h>
#include <cstdint>
#include <math.h>

#define Bz 2
#define Sz 2048
#define Dz 1024
#define Hz 16
#define DHz 64
#define NROW (Bz*Sz)   // 4096

typedef __nv_bfloat16  bf16;
typedef __nv_bfloat162 bf162;

// ---------------- device scratch (no allocations allowed) -------------------
__device__ bf16 g_xh[3u*NROW*Dz];   // split q,k,v inputs
__device__ bf16 g_xl[3u*NROW*Dz];
__device__ bf16 g_wh[4u*Dz*Dz];     // split wq,wk,wv,wd
__device__ bf16 g_wl[4u*Dz*Dz];
__device__ bf16 g_qh[Bz*Hz*Sz*DHz]; // projected, split-head [B,H,S,DH]
__device__ bf16 g_ql[Bz*Hz*Sz*DHz];
__device__ bf16 g_kh[Bz*Hz*Sz*DHz];
__device__ bf16 g_kl[Bz*Hz*Sz*DHz];
__device__ bf16 g_vth[Bz*Hz*DHz*Sz]; // V transposed [B,H,DH,S]
__device__ bf16 g_vtl[Bz*Hz*DHz*Sz];
__device__ bf16 g_ah[NROW*Dz];      // attention out (merged heads), split
__device__ bf16 g_al[NROW*Dz];
__device__ uint32_t g_mp[Bz*Sz*(Sz/32)]; // bit-packed mask
__device__ float g_inv[Bz*Hz*Sz];

// ---------------- helpers ---------------------------------------------------
__device__ __forceinline__ uint32_t packbf(float a, float b){
    bf162 t = __floats2bfloat162_rn(a, b);
    return *reinterpret_cast<uint32_t*>(&t);
}
__device__ __forceinline__ uint32_t smem_u32(const void* p){
    uint32_t a;
    asm("{ .reg .u64 t; cvta.to.shared.u64 t, %1; cvt.u32.u64 %0, t; }"
        : "=r"(a) : "l"(p));
    return a;
}
__device__ __forceinline__ void mma16816(float* d, const uint32_t* a, const uint32_t* b){
    asm volatile("mma.sync.aligned.m16n8k16.row.col.f32.bf16.bf16.f32 "
        "{%0,%1,%2,%3}, {%4,%5,%6,%7}, {%8,%9}, {%0,%1,%2,%3};"
        : "+f"(d[0]), "+f"(d[1]), "+f"(d[2]), "+f"(d[3])
        : "r"(a[0]), "r"(a[1]), "r"(a[2]), "r"(a[3]), "r"(b[0]), "r"(b[1]));
}
#define CP16(dst, src) \
    asm volatile("cp.async.cg.shared.global [%0], [%1], 16;" :: "r"(dst), "l"(src))
#define CP_COMMIT() asm volatile("cp.async.commit_group;" ::: "memory")
#define CP_WAIT(n)  asm volatile("cp.async.wait_group %0;" :: "n"(n) : "memory")

#define ZERO_ACC(a, NAT) \
    _Pragma("unroll") for (int _i=0;_i<4;_i++) \
    _Pragma("unroll") for (int _j=0;_j<NAT;_j++) \
    _Pragma("unroll") for (int _k=0;_k<4;_k++) a[_i][_j][_k] = 0.f;

// ---------------- prep: fp32 -> bf16 hi/lo split ----------------------------
__global__ __launch_bounds__(256)
void split_arr(const float4* __restrict__ s, bf16* __restrict__ dh,
               bf16* __restrict__ dl, int n4)
{
    int i = blockIdx.x*256 + threadIdx.x;
    if (i >= n4) return;
    float4 x = s[i];
    float hx = __bfloat162float(__float2bfloat16(x.x));
    float hy = __bfloat162float(__float2bfloat16(x.y));
    float hz = __bfloat162float(__float2bfloat16(x.z));
    float hw = __bfloat162float(__float2bfloat16(x.w));
    ((uint32_t*)dh)[2*i]   = packbf(hx, hy);
    ((uint32_t*)dh)[2*i+1] = packbf(hz, hw);
    ((uint32_t*)dl)[2*i]   = packbf(x.x-hx, x.y-hy);
    ((uint32_t*)dl)[2*i+1] = packbf(x.z-hz, x.w-hw);
}

// ---------------- prep: bit-pack mask ---------------------------------------
__global__ __launch_bounds__(256)
void maskpack(const int* __restrict__ mask)
{
    int row = blockIdx.x*4 + (threadIdx.x >> 6);  // 0..4095
    int w   = threadIdx.x & 63;
    const int4* p = (const int4*)(mask + (size_t)row*Sz + w*32);
    uint32_t bits = 0;
#pragma unroll
    for (int i = 0; i < 8; i++){
        int4 m = p[i];
        bits |= (m.x?1u:0u) << (i*4)
             |  (m.y?1u:0u) << (i*4+1)
             |  (m.z?1u:0u) << (i*4+2)
             |  (m.w?1u:0u) << (i*4+3);
    }
    g_mp[(size_t)row*64 + w] = bits;
}

// ---------------- GEMM v2 mainloop (NT, bf16 hi/lo operands) ---------------
// BM=128, BN=128, BK=32, 256 threads, double-buffered cp.async.
// Stage layout (words): AH 0, AL 2560, BH 5120, BL 7680; stage = 10240 w.
__device__ __forceinline__ void gemm_v2(
    const bf16* __restrict__ Ah, const bf16* __restrict__ Al, int lda,
    const bf16* __restrict__ Bh, const bf16* __restrict__ Bl, int ldb,
    int K, uint32_t* sm, float acc[4][4][4], int tid)
{
    const uint32_t base = smem_u32(sm);
    const int wid = tid>>5, lane = tid&31;
    const int wm = (wid>>2)*64, wn = (wid&3)*32;
    const int gid = lane>>2, qid = lane&3;
    const int NC = K/32;

    auto issue = [&](int c, int st){
        uint32_t so = base + (uint32_t)st*10240u*4u;
#pragma unroll
        for (int i=0;i<2;i++){
            int q = i*256+tid, r = q>>2, ch = q&3;
            CP16(so + (r*20 + ch*4)*4,          Ah + (size_t)r*lda + c*32 + ch*8);
            CP16(so + (2560 + r*20 + ch*4)*4,   Al + (size_t)r*lda + c*32 + ch*8);
            CP16(so + (5120 + r*20 + ch*4)*4,   Bh + (size_t)r*ldb + c*32 + ch*8);
            CP16(so + (7680 + r*20 + ch*4)*4,   Bl + (size_t)r*ldb + c*32 + ch*8);
        }
    };

    issue(0,0); CP_COMMIT();

    for (int c = 0; c < NC; c++){
        if (c+1 < NC){ issue(c+1,(c+1)&1); CP_COMMIT(); CP_WAIT(1); }
        else         { CP_WAIT(0); }
        __syncthreads();

        const uint32_t* S = sm + (c&1)*10240;
        const uint32_t* sAh = S;
        const uint32_t* sAl = S + 2560;
        const uint32_t* sBh = S + 5120;
        const uint32_t* sBl = S + 7680;
#pragma unroll
        for (int c16 = 0; c16 < 2; c16++){
            const int w0 = c16*8 + qid;
            uint32_t aH[4][4], aL[4][4];
#pragma unroll
            for (int mi=0;mi<4;mi++){
                int r0 = wm + mi*16 + gid;
                aH[mi][0]=sAh[r0*20+w0];   aH[mi][1]=sAh[(r0+8)*20+w0];
                aH[mi][2]=sAh[r0*20+w0+4]; aH[mi][3]=sAh[(r0+8)*20+w0+4];
                aL[mi][0]=sAl[r0*20+w0];   aL[mi][1]=sAl[(r0+8)*20+w0];
                aL[mi][2]=sAl[r0*20+w0+4]; aL[mi][3]=sAl[(r0+8)*20+w0+4];
            }
            uint32_t bH[4][2], bL[4][2];
#pragma unroll
            for (int ni=0;ni<4;ni++){
                int rn = wn + ni*8 + gid;
                bH[ni][0]=sBh[rn*20+w0]; bH[ni][1]=sBh[rn*20+w0+4];
                bL[ni][0]=sBl[rn*20+w0]; bL[ni][1]=sBl[rn*20+w0+4];
            }
#pragma unroll
            for (int mi=0;mi<4;mi++)
#pragma unroll
                for (int ni=0;ni<4;ni++){
                    mma16816(acc[mi][ni], aH[mi], bH[ni]);
                    mma16816(acc[mi][ni], aH[mi], bL[ni]);
                    mma16816(acc[mi][ni], aL[mi], bH[ni]);
                }
        }
        __syncthreads();
    }
}

// stage accumulators -> fp32 smem tile [128][132]
__device__ __forceinline__ void stage_acc128(float* stg, float acc[4][4][4],
                                             int tid, const float* bias_s)
{
    const int wid = tid>>5, lane = tid&31;
    const int wm = (wid>>2)*64, wn = (wid&3)*32;
    const int gid = lane>>2, qid = lane&3;
#pragma unroll
    for (int mi=0;mi<4;mi++)
#pragma unroll
        for (int ni=0;ni<4;ni++){
            int r = wm + mi*16 + gid;
            int cc = wn + ni*8 + qid*2;
            float b0 = bias_s ? bias_s[cc]   : 0.f;
            float b1 = bias_s ? bias_s[cc+1] : 0.f;
            stg[(size_t)r*132 + cc]       = acc[mi][ni][0] + b0;
            stg[(size_t)r*132 + cc+1]     = acc[mi][ni][1] + b1;
            stg[(size_t)(r+8)*132 + cc]   = acc[mi][ni][2] + b0;
            stg[(size_t)(r+8)*132 + cc+1] = acc[mi][ni][3] + b1;
        }
}

// ---------------- projections: Y = X @ W^T + b -> split-head hi/lo bf16 ----
__global__ __launch_bounds__(256)
void proj_tc(const float* __restrict__ bq, const float* __restrict__ bk,
             const float* __restrict__ bv)
{
    extern __shared__ uint32_t sm[];
    __shared__ float bias_s[128];
    const int tid = threadIdx.x;
    const int which = blockIdx.z;
    const int bn = blockIdx.x*128, bm = blockIdx.y*128;

    const bf16* Ah = g_xh + (size_t)which*NROW*Dz + (size_t)bm*Dz;
    const bf16* Al = g_xl + (size_t)which*NROW*Dz + (size_t)bm*Dz;
    const bf16* Bh = g_wh + (size_t)which*Dz*Dz + (size_t)bn*Dz;
    const bf16* Bl = g_wl + (size_t)which*Dz*Dz + (size_t)bn*Dz;
    const float* bias = (which==0) ? bq : (which==1) ? bk : bv;
    if (tid < 128) bias_s[tid] = bias[bn + tid];
    __syncthreads();

    float acc[4][4][4]; ZERO_ACC(acc, 4);
    gemm_v2(Ah, Al, Dz, Bh, Bl, Dz, Dz, sm, acc, tid);

    float* stg = (float*)sm;
    stage_acc128(stg, acc, tid, bias_s);
    __syncthreads();

    if (which == 2){
        // transposed: g_vt*[b,h,dh,s]
        for (int i=0;i<64;i++){
            int idx = i*256 + tid;
            int r = idx & 127, c = idx >> 7;
            float vv = stg[(size_t)r*132 + c];
            int m = bm + r, b = m>>11, s = m & 2047;
            int col = bn + c, h = col>>6, dh = col&63;
            size_t di = (((size_t)b*Hz + h)*DHz + dh)*Sz + s;
            bf16 hh = __float2bfloat16(vv);
            g_vth[di] = hh;
            g_vtl[di] = __float2bfloat16(vv - __bfloat162float(hh));
        }
    } else {
        bf16* dh = which ? g_kh : g_qh;
        bf16* dl = which ? g_kl : g_ql;
        for (int i=0;i<16;i++){
            int f = i*256 + tid, r = f>>5, c4 = f&31;
            float4 x = *(float4*)&stg[(size_t)r*132 + c4*4];
            int m = bm + r, b = m>>11, s = m & 2047;
            int col = bn + c4*4, h = col>>6, dh_ = col&63;
            size_t di = (((size_t)b*Hz + h)*Sz + s)*DHz + dh_;
            float hx = __bfloat162float(__float2bfloat16(x.x));
            float hy = __bfloat162float(__float2bfloat16(x.y));
            float hz = __bfloat162float(__float2bfloat16(x.z));
            float hw = __bfloat162float(__float2bfloat16(x.w));
            ((uint32_t*)&dh[di])[0] = packbf(hx, hy);
            ((uint32_t*)&dh[di])[1] = packbf(hz, hw);
            ((uint32_t*)&dl[di])[0] = packbf(x.x-hx, x.y-hy);
            ((uint32_t*)&dl[di])[1] = packbf(x.z-hz, x.w-hw);
        }
    }
}

// ---------------- fused attention -------------------------------------------
// smem (words): QH 0, QL 4608; K stage st: 9216+st*9216 (KH +0, KL +4608);
// V stage st: 27648+st*8704 (VH +0, VL +4352). Total 45056 w = 180224 B.
#define FO_Q  0
#define FO_K  9216
#define FO_V  27648
#define F_SMEM_BYTES 180224

__global__ __launch_bounds__(256)
void attn_fused(float* __restrict__ Wout)
{
    extern __shared__ uint32_t sm[];
    const uint32_t base = smem_u32(sm);
    const int tid = threadIdx.x, lane = tid&31, wid = tid>>5;
    const int gid = lane>>2, qid = lane&3;
    const int bh = blockIdx.y, b = bh>>4, h = bh&15;
    const int bm = blockIdx.x*128;
    const int wr = wid*16;

    auto load_kv = [&](int j, int st){
        const int bn = j*128;
        uint32_t ko = base + (FO_K + st*9216)*4;
#pragma unroll
        for (int i=0;i<4;i++){
            int q = i*256+tid, r = q>>3, ch = q&7;
            CP16(ko + (r*36 + ch*4)*4,        g_kh + ((size_t)bh*Sz + bn + r)*DHz + ch*8);
            CP16(ko + (4608 + r*36 + ch*4)*4, g_kl + ((size_t)bh*Sz + bn + r)*DHz + ch*8);
        }
        uint32_t vo = base + (FO_V + st*8704)*4;
#pragma unroll
        for (int i=0;i<4;i++){
            int q = i*256+tid, r = q>>4, ch = q&15;
            CP16(vo + (r*68 + ch*4)*4,        g_vth + ((size_t)bh*DHz + r)*Sz + bn + ch*8);
            CP16(vo + (4352 + r*68 + ch*4)*4, g_vtl + ((size_t)bh*DHz + r)*Sz + bn + ch*8);
        }
    };

    // Q preload (persistent) + first K/V stage in one group
#pragma unroll
    for (int i=0;i<4;i++){
        int q = i*256+tid, r = q>>3, ch = q&7;
        CP16(base + (FO_Q + r*36 + ch*4)*4,        g_qh + ((size_t)bh*Sz + bm + r)*DHz + ch*8);
        CP16(base + (FO_Q + 4608 + r*36 + ch*4)*4, g_ql + ((size_t)bh*Sz + bm + r)*DHz + ch*8);
    }
    load_kv(0, 0);
    CP_COMMIT();

    float O[8][4];
#pragma unroll
    for (int i=0;i<8;i++){ O[i][0]=0.f; O[i][1]=0.f; O[i][2]=0.f; O[i][3]=0.f; }
    float s0 = 0.f, s1 = 0.f;

    for (int j = 0; j < 16; j++){
        if (j < 15){ load_kv(j+1, (j+1)&1); CP_COMMIT(); CP_WAIT(1); }
        else       { CP_WAIT(0); }
        __syncthreads();

        const uint32_t* KH = sm + FO_K + (j&1)*9216;
        const uint32_t* KL = KH + 4608;
        const uint32_t* VH = sm + FO_V + (j&1)*8704;
        const uint32_t* VL = VH + 4352;
        const int bn = j*128;

        // ----- scores MMA -----
        float e4[16][4];
#pragma unroll
        for (int ni=0;ni<16;ni++){ e4[ni][0]=0.f; e4[ni][1]=0.f; e4[ni][2]=0.f; e4[ni][3]=0.f; }
#pragma unroll
        for (int c16=0;c16<4;c16++){
            const int w0 = c16*8 + qid;
            uint32_t aH[4], aL[4];
            const int r0 = wr + gid;
            aH[0]=sm[FO_Q + r0*36 + w0];     aH[1]=sm[FO_Q + (r0+8)*36 + w0];
            aH[2]=sm[FO_Q + r0*36 + w0+4];   aH[3]=sm[FO_Q + (r0+8)*36 + w0+4];
            aL[0]=sm[FO_Q+4608 + r0*36 + w0];   aL[1]=sm[FO_Q+4608 + (r0+8)*36 + w0];
            aL[2]=sm[FO_Q+4608 + r0*36 + w0+4]; aL[3]=sm[FO_Q+4608 + (r0+8)*36 + w0+4];
#pragma unroll
            for (int ni=0;ni<16;ni++){
                const int rn = ni*8 + gid;
                uint32_t bH[2], bL[2];
                bH[0]=KH[rn*36 + w0]; bH[1]=KH[rn*36 + w0+4];
                bL[0]=KL[rn*36 + w0]; bL[1]=KL[rn*36 + w0+4];
                mma16816(e4[ni], aH, bH);
                mma16816(e4[ni], aH, bL);
                mma16816(e4[ni], aL, bH);
            }
        }

        // ----- mask(bits) + exp + rowsum + pack + direct e write -----
        const uint32_t* mp0 = g_mp + ((size_t)b*Sz + bm + wr + gid)*64 + j*4;
        uint4 mwa = *(const uint4*)mp0;
        uint4 mwb = *(const uint4*)(mp0 + 8*64);
        float* Wrow = Wout + ((size_t)bh*Sz + bm + wr + gid)*Sz + bn;

        uint32_t Ahi[8][4], Alo[8][4];
#pragma unroll
        for (int ni=0;ni<16;ni++){
            uint32_t wa = (ni<4)?mwa.x:(ni<8)?mwa.y:(ni<12)?mwa.z:mwa.w;
            uint32_t wb = (ni<4)?mwb.x:(ni<8)?mwb.y:(ni<12)?mwb.z:mwb.w;
            int sh = (ni&3)*8 + 2*qid;
            float v0 = ((wa>>sh)&1u)     ? __expf(e4[ni][0]*0.125f) : 0.f;
            float v1 = ((wa>>(sh+1))&1u) ? __expf(e4[ni][1]*0.125f) : 0.f;
            float v2 = ((wb>>sh)&1u)     ? __expf(e4[ni][2]*0.125f) : 0.f;
            float v3 = ((wb>>(sh+1))&1u) ? __expf(e4[ni][3]*0.125f) : 0.f;
            s0 += v0 + v1;  s1 += v2 + v3;
            *(float2*)(Wrow + ni*8 + 2*qid)            = make_float2(v0, v1);
            *(float2*)(Wrow + (size_t)8*Sz + ni*8 + 2*qid) = make_float2(v2, v3);
            float h0 = __bfloat162float(__float2bfloat16(v0));
            float h1 = __bfloat162float(__float2bfloat16(v1));
            float h2 = __bfloat162float(__float2bfloat16(v2));
            float h3 = __bfloat162float(__float2bfloat16(v3));
            int kc = ni>>1, hl = (ni&1)*2;
            Ahi[kc][hl]   = packbf(h0, h1);
            Ahi[kc][hl+1] = packbf(h2, h3);
            Alo[kc][hl]   = packbf(v0-h0, v1-h1);
            Alo[kc][hl+1] = packbf(v2-h2, v3-h3);
        }

        // ----- AV MMA -----
#pragma unroll
        for (int kc=0;kc<8;kc++){
            const int w0 = kc*8 + qid;
#pragma unroll
            for (int nf=0;nf<8;nf++){
                const int rn = nf*8 + gid;
                uint32_t bH[2], bL[2];
                bH[0]=VH[rn*68 + w0]; bH[1]=VH[rn*68 + w0+4];
                bL[0]=VL[rn*68 + w0]; bL[1]=VL[rn*68 + w0+4];
                mma16816(O[nf], Ahi[kc], bH);
                mma16816(O[nf], Ahi[kc], bL);
                mma16816(O[nf], Alo[kc], bH);
            }
        }
        __syncthreads();
    }

    // rowsums -> inverse
    s0 += __shfl_xor_sync(0xffffffffu, s0, 1);
    s0 += __shfl_xor_sync(0xffffffffu, s0, 2);
    s1 += __shfl_xor_sync(0xffffffffu, s1, 1);
    s1 += __shfl_xor_sync(0xffffffffu, s1, 2);
    const float inv0 = 1.0f / s0, inv1 = 1.0f / s1;
    if (qid == 0){
        g_inv[(size_t)bh*Sz + bm + wr + gid]     = inv0;
        g_inv[(size_t)bh*Sz + bm + wr + gid + 8] = inv1;
    }

    // normalized O -> g_ah/g_al (bf16 hi/lo), direct stores
    size_t i0 = ((size_t)b*Sz + bm + wr + gid)*Dz + h*DHz + 2*qid;
    size_t i1 = i0 + (size_t)8*Dz;
#pragma unroll
    for (int nf=0;nf<8;nf++){
        float o0 = O[nf][0]*inv0, o1 = O[nf][1]*inv0;
        float o2 = O[nf][2]*inv1, o3 = O[nf][3]*inv1;
        float h0 = __bfloat162float(__float2bfloat16(o0));
        float h1 = __bfloat162float(__float2bfloat16(o1));
        float h2 = __bfloat162float(__float2bfloat16(o2));
        float h3 = __bfloat162float(__float2bfloat16(o3));
        *(uint32_t*)&g_ah[i0 + nf*8] = packbf(h0, h1);
        *(uint32_t*)&g_al[i0 + nf*8] = packbf(o0-h0, o1-h1);
        *(uint32_t*)&g_ah[i1 + nf*8] = packbf(h2, h3);
        *(uint32_t*)&g_al[i1 + nf*8] = packbf(o2-h2, o3-h3);
    }
}

// ---------------- normalize weights: w *= inv[row] -------------------------
__global__ __launch_bounds__(256)
void norm_weights(float* __restrict__ Wt)
{
    const size_t row = blockIdx.x;
    const float inv = g_inv[row];
    float4* p = (float4*)(Wt + row*(size_t)Sz);
    float4 a = p[threadIdx.x];
    float4 b = p[threadIdx.x + 256];
    a.x*=inv; a.y*=inv; a.z*=inv; a.w*=inv;
    b.x*=inv; b.y*=inv; b.z*=inv; b.w*=inv;
    p[threadIdx.x] = a;
    p[threadIdx.x + 256] = b;
}

// ---------------- dense: out = attn @ W^T + b ------------------------------
__global__ __launch_bounds__(256)
void dense_tc(const float* __restrict__ bias, float* __restrict__ C)
{
    extern __shared__ uint32_t sm[];
    __shared__ float bias_s[128];
    const int tid = threadIdx.x;
    const int bn = blockIdx.x*128, bm = blockIdx.y*128;
    if (tid < 128) bias_s[tid] = bias[bn + tid];
    __syncthreads();

    float acc[4][4][4]; ZERO_ACC(acc, 4);
    gemm_v2(g_ah + (size_t)bm*Dz, g_al + (size_t)bm*Dz, Dz,
            g_wh + (size_t)3*Dz*Dz + (size_t)bn*Dz,
            g_wl + (size_t)3*Dz*Dz + (size_t)bn*Dz, Dz, Dz, sm, acc, tid);

    float* stg = (float*)sm;
    stage_acc128(stg, acc, tid, bias_s);
    __syncthreads();

    for (int i=0;i<16;i++){
        int f = i*256 + tid, r = f>>5, c4 = f&31;
        float4 v = *(float4*)&stg[(size_t)r*132 + c4*4];
        *(float4*)&C[(size_t)(bm + r)*Dz + bn + c4*4] = v;
    }
}

// ---------------------------------------------------------------------------
#define SMEM_GEMM 81920

extern "C" void kernel_launch(void* const* d_in, const int* in_sizes, int n_in,
                              void* d_out, int out_size)
{
    const float* q    = (const float*)d_in[0];
    const float* k    = (const float*)d_in[1];
    const float* v    = (const float*)d_in[2];
    const int*   mask = (const int*)  d_in[3];
    const float* wq_w = (const float*)d_in[4];
    const float* wq_b = (const float*)d_in[5];
    const float* wk_w = (const float*)d_in[6];
    const float* wk_b = (const float*)d_in[7];
    const float* wv_w = (const float*)d_in[8];
    const float* wv_b = (const float*)d_in[9];
    const float* dw   = (const float*)d_in[10];
    const float* db   = (const float*)d_in[11];

    float* out     = (float*)d_out;                 // [B,S,D]
    float* weights = out + (size_t)Bz * Sz * Dz;    // [B,H,S,S]

    cudaFuncSetAttribute(proj_tc,    cudaFuncAttributeMaxDynamicSharedMemorySize, SMEM_GEMM);
    cudaFuncSetAttribute(attn_fused, cudaFuncAttributeMaxDynamicSharedMemorySize, F_SMEM_BYTES);
    cudaFuncSetAttribute(dense_tc,   cudaFuncAttributeMaxDynamicSharedMemorySize, SMEM_GEMM);

    // resolve device scratch addresses (host side, graph-safe)
    bf16 *xh, *xl, *wh, *wl;
    cudaGetSymbolAddress((void**)&xh, g_xh);
    cudaGetSymbolAddress((void**)&xl, g_xl);
    cudaGetSymbolAddress((void**)&wh, g_wh);
    cudaGetSymbolAddress((void**)&wl, g_wl);

    const int n4x = NROW*Dz/4;        // 1048576
    const int n4w = Dz*Dz/4;          // 262144
    split_arr<<<(n4x+255)/256, 256>>>((const float4*)q, xh,            xl,            n4x);
    split_arr<<<(n4x+255)/256, 256>>>((const float4*)k, xh + (size_t)NROW*Dz,   xl + (size_t)NROW*Dz,   n4x);
    split_arr<<<(n4x+255)/256, 256>>>((const float4*)v, xh + (size_t)2*NROW*Dz, xl + (size_t)2*NROW*Dz, n4x);
    split_arr<<<(n4w+255)/256, 256>>>((const float4*)wq_w, wh,                    wl,                    n4w);
    split_arr<<<(n4w+255)/256, 256>>>((const float4*)wk_w, wh + (size_t)Dz*Dz,    wl + (size_t)Dz*Dz,    n4w);
    split_arr<<<(n4w+255)/256, 256>>>((const float4*)wv_w, wh + (size_t)2*Dz*Dz,  wl + (size_t)2*Dz*Dz,  n4w);
    split_arr<<<(n4w+255)/256, 256>>>((const float4*)dw,   wh + (size_t)3*Dz*Dz,  wl + (size_t)3*Dz*Dz,  n4w);
    maskpack<<<NROW/4*4/4, 256>>>(mask);   // 1024 blocks * 4 rows = 4096 rows

    dim3 gProj(Dz/128, NROW/128, 3);          // (8, 32, 3)
    proj_tc<<<gProj, 256, SMEM_GEMM>>>(wq_b, wk_b, wv_b);

    dim3 gF(Sz/128, Bz*Hz);                   // (16, 32)
    attn_fused<<<gF, 256, F_SMEM_BYTES>>>(weights);

    norm_weights<<<Bz*Hz*Sz, 256>>>(weights);

    dim3 gDn(Dz/128, NROW/128);               // (8, 32)
    dense_tc<<<gDn, 256, SMEM_GEMM>>>(db, out);
}